// round 2
// baseline (speedup 1.0000x reference)
#include <cuda_runtime.h>
#include <cuda_bf16.h>

// ConsecutiveLoss: x [4096, 8192] fp32 -> scalar
//   rl[i]      = count of nonzeros in row i
//   per_row[i] = sum_{p=1}^{rl[i]-1} |x[i,p]-x[i,p-1]| / rl[i]
//   out        = sum_{i>=1} per_row[i] / 4096      (row 0 skipped — faithful quirk)
//
// One CTA per row; row staged in SMEM so the mask (p < rl) can be applied
// after counting nonzeros with only ONE HBM pass. Deterministic: per-row
// results land in a __device__ scratch array, reduced by a second kernel.

#define BSZ      4096
#define SEQ      8192
#define THREADS  256
#define VEC_PER_THREAD (SEQ / 4 / THREADS)   // 8 float4 per thread

__device__ float g_row_loss[BSZ];

__global__ __launch_bounds__(THREADS)
void consecutive_row_kernel(const float* __restrict__ x) {
    __shared__ float s[SEQ];          // 32 KB row stage
    __shared__ int   cred[THREADS / 32];
    __shared__ float fred[THREADS / 32];
    __shared__ int   rl_sh;

    const int row = blockIdx.x;
    const int t   = threadIdx.x;

    // ---- Pass A: vectorized coalesced streaming load -> SMEM, count nonzeros ----
    const float4* xr = reinterpret_cast<const float4*>(x + (size_t)row * SEQ);
    float4*       sv = reinterpret_cast<float4*>(s);
    int cnt = 0;
    #pragma unroll
    for (int k = 0; k < VEC_PER_THREAD; ++k) {
        const int i = t + k * THREADS;          // coalesced across warp
        float4 v = __ldcs(&xr[i]);              // evict-first: data touched once
        sv[i] = v;
        cnt += (v.x != 0.0f) + (v.y != 0.0f) + (v.z != 0.0f) + (v.w != 0.0f);
    }

    // warp reduce count
    #pragma unroll
    for (int o = 16; o > 0; o >>= 1) cnt += __shfl_xor_sync(0xFFFFFFFFu, cnt, o);
    if ((t & 31) == 0) cred[t >> 5] = cnt;
    __syncthreads();                            // also fences all s[] stores

    if (t < 32) {
        int c = (t < THREADS / 32) ? cred[t] : 0;
        #pragma unroll
        for (int o = 4; o > 0; o >>= 1) c += __shfl_xor_sync(0xFFFFFFFFu, c, o);
        if (t == 0) rl_sh = c;
    }
    __syncthreads();
    const int rl = rl_sh;

    // ---- Pass B: masked |diff| sum from SMEM (bank-conflict-free stride) ----
    // p ranges over t+1 + 256k; max p == SEQ only when t==255,k==31, and then
    // p < rl is necessarily false (rl <= SEQ), so no separate bounds check.
    float sum = 0.0f;
    #pragma unroll
    for (int k = 0; k < SEQ / THREADS; ++k) {
        const int p = t + 1 + k * THREADS;
        if (p < rl)
            sum += fabsf(s[p] - s[p - 1]);
    }

    // warp reduce sum
    #pragma unroll
    for (int o = 16; o > 0; o >>= 1) sum += __shfl_xor_sync(0xFFFFFFFFu, sum, o);
    if ((t & 31) == 0) fred[t >> 5] = sum;
    __syncthreads();

    if (t < 32) {
        float v = (t < THREADS / 32) ? fred[t] : 0.0f;
        #pragma unroll
        for (int o = 4; o > 0; o >>= 1) v += __shfl_xor_sync(0xFFFFFFFFu, v, o);
        if (t == 0) {
            // Faithful: divide by rl (nan if rl==0, like reference); row 0 masked out.
            float per_row = v / (float)rl;
            g_row_loss[row] = (row >= 1) ? per_row : 0.0f;
        }
    }
}

__global__ __launch_bounds__(1024)
void consecutive_final_kernel(float* __restrict__ out) {
    __shared__ float fred[32];
    const int t = threadIdx.x;
    float sum = 0.0f;
    #pragma unroll
    for (int i = t; i < BSZ; i += 1024) sum += __ldca(&g_row_loss[i]);
    #pragma unroll
    for (int o = 16; o > 0; o >>= 1) sum += __shfl_xor_sync(0xFFFFFFFFu, sum, o);
    if ((t & 31) == 0) fred[t >> 5] = sum;
    __syncthreads();
    if (t < 32) {
        float v = fred[t];
        #pragma unroll
        for (int o = 16; o > 0; o >>= 1) v += __shfl_xor_sync(0xFFFFFFFFu, v, o);
        if (t == 0) out[0] = v / (float)BSZ;
    }
}

extern "C" void kernel_launch(void* const* d_in, const int* in_sizes, int n_in,
                              void* d_out, int out_size) {
    (void)in_sizes; (void)n_in; (void)out_size;
    const float* x   = (const float*)d_in[0];
    float*       out = (float*)d_out;

    consecutive_row_kernel<<<BSZ, THREADS>>>(x);
    consecutive_final_kernel<<<1, 1024>>>(out);
}

// round 3
// speedup vs baseline: 1.0478x; 1.0478x over previous
#include <cuda_runtime.h>
#include <cuda_bf16.h>

// ConsecutiveLoss: x [4096, 8192] fp32 -> scalar
//   rl[i]      = count of nonzeros in row i
//   per_row[i] = sum_{p=1}^{rl[i]-1} |x[i,p]-x[i,p-1]| / rl[i]
//   out        = sum_{i>=1} per_row[i] / 4096      (row 0 skipped — faithful quirk)
//
// Single-pass register-resident design:
//   * accumulate UNMASKED |diff| sum + nonzero count while streaming the row
//     (cross-lane diffs via shfl_up; 64 warp/iter boundary elems via tiny smem)
//   * mask (p < rl) is a prefix -> masked = unmasked - tail correction;
//     correction re-reads only positions >= rl (never taken for rl == SEQ)
//   * last-CTA-done pattern fuses the final 4096-row reduction (int atomic
//     ticket = deterministic; float reduction in one CTA, fixed order)

#define BSZ      4096
#define SEQ      8192
#define THREADS  256
#define NWARP    (THREADS / 32)              // 8
#define VEC      (SEQ / 4 / THREADS)         // 8 float4 per thread
#define NSLOT    (NWARP * VEC)               // 64 boundary slots per CTA

__device__ float        g_row_loss[BSZ];
__device__ unsigned int g_done;              // zero-initialized at load

__global__ __launch_bounds__(THREADS)
void consecutive_fused_kernel(const float* __restrict__ x, float* __restrict__ out) {
    __shared__ float bprev[NSLOT + 1];       // elem 128*s - 1, for boundary diff at e=128*s
    __shared__ float firstx[NSLOT];          // elem 128*s
    __shared__ int   cred[NWARP];
    __shared__ float fred[NWARP];
    __shared__ int   rl_sh;
    __shared__ int   last_flag;

    const int row  = blockIdx.x;
    const int t    = threadIdx.x;
    const int lane = t & 31;
    const int w    = t >> 5;

    // ---- Single streaming pass: coalesced float4 loads, unmasked diffs + count ----
    const float4* xr = reinterpret_cast<const float4*>(x + (size_t)row * SEQ);
    int   cnt = 0;
    float sum = 0.0f;
    #pragma unroll
    for (int k = 0; k < VEC; ++k) {
        const int i = t + k * THREADS;                   // float4 idx; elems 4i..4i+3
        float4 v = __ldcs(&xr[i]);                       // streaming, touched once
        cnt += (v.x != 0.0f) + (v.y != 0.0f) + (v.z != 0.0f) + (v.w != 0.0f);
        // 3 internal diffs
        sum += fabsf(v.y - v.x) + fabsf(v.z - v.y) + fabsf(v.w - v.z);
        // diff at e = 4i vs neighbor lane's v.w (same k)
        float pw = __shfl_up_sync(0xFFFFFFFFu, v.w, 1);
        if (lane > 0) sum += fabsf(v.x - pw);
        // warp/iteration boundaries handled via smem: slot s = w + NWARP*k
        if (lane == 0)  firstx[w + NWARP * k]    = v.x;  // elem 128*s
        if (lane == 31) bprev[w + NWARP * k + 1] = v.w;  // elem 128*(s+1) - 1
    }

    // warp-reduce count
    #pragma unroll
    for (int o = 16; o > 0; o >>= 1) cnt += __shfl_xor_sync(0xFFFFFFFFu, cnt, o);
    if (lane == 0) cred[w] = cnt;
    __syncthreads();

    // boundary diffs at e = 128*s, s = 1..63 (all < SEQ, unmasked)
    if (t >= 1 && t < NSLOT)
        sum += fabsf(firstx[t] - bprev[t]);

    if (t < 32) {
        int c = (t < NWARP) ? cred[t] : 0;
        #pragma unroll
        for (int o = 4; o > 0; o >>= 1) c += __shfl_xor_sync(0xFFFFFFFFu, c, o);
        if (t == 0) rl_sh = c;
    }
    __syncthreads();
    const int rl = rl_sh;

    // ---- Rare tail correction: subtract diffs at positions e in [max(rl,1), SEQ) ----
    if (rl < SEQ) {
        const float* xrow = x + (size_t)row * SEQ;
        const int e0 = (rl < 1) ? 1 : rl;
        for (int e = e0 + t; e < SEQ; e += THREADS)
            sum -= fabsf(xrow[e] - xrow[e - 1]);
    }

    // ---- Block-reduce masked sum ----
    #pragma unroll
    for (int o = 16; o > 0; o >>= 1) sum += __shfl_xor_sync(0xFFFFFFFFu, sum, o);
    if (lane == 0) fred[w] = sum;
    __syncthreads();
    if (t < 32) {
        float v = (t < NWARP) ? fred[t] : 0.0f;
        #pragma unroll
        for (int o = 4; o > 0; o >>= 1) v += __shfl_xor_sync(0xFFFFFFFFu, v, o);
        if (t == 0) {
            float per_row = v / (float)rl;               // nan if rl==0 (faithful)
            g_row_loss[row] = (row >= 1) ? per_row : 0.0f;
        }
    }

    // ---- Last-CTA-done: fused final reduction (deterministic order) ----
    if (t == 0) {
        __threadfence();                                 // publish g_row_loss[row]
        unsigned old = atomicAdd(&g_done, 1u);
        last_flag = (old == (unsigned)(gridDim.x - 1));
    }
    __syncthreads();
    if (last_flag) {
        float tot = 0.0f;
        #pragma unroll
        for (int i = t; i < BSZ; i += THREADS)
            tot += __ldcg(&g_row_loss[i]);               // L2, bypass own L1
        #pragma unroll
        for (int o = 16; o > 0; o >>= 1) tot += __shfl_xor_sync(0xFFFFFFFFu, tot, o);
        if (lane == 0) fred[w] = tot;
        __syncthreads();
        if (t < 32) {
            float v = (t < NWARP) ? fred[t] : 0.0f;
            #pragma unroll
            for (int o = 4; o > 0; o >>= 1) v += __shfl_xor_sync(0xFFFFFFFFu, v, o);
            if (t == 0) {
                out[0] = v / (float)BSZ;
                g_done = 0;                              // re-arm for next replay
            }
        }
    }
}

extern "C" void kernel_launch(void* const* d_in, const int* in_sizes, int n_in,
                              void* d_out, int out_size) {
    (void)in_sizes; (void)n_in; (void)out_size;
    const float* x   = (const float*)d_in[0];
    float*       out = (float*)d_out;

    consecutive_fused_kernel<<<BSZ, THREADS>>>(x, out);
}